// round 2
// baseline (speedup 1.0000x reference)
#include <cuda_runtime.h>
#include <cuda_bf16.h>

// Problem: B=2, S=2048, D=1024, H=16, Dh=64, fp32.
// out = W_O-proj( causal-softmax( (R Wq^T)(R Wk^T)^T / 8 ) (R Wv^T) )

#define B_   2
#define S_   2048
#define D_   1024
#define H_   16
#define DH_  64
#define M_   (B_ * S_)          // 4096 rows

#define QKV_ELEMS (B_ * S_ * H_ * DH_)   // 4,194,304 floats = 16 MB

// Scratch (allocation-free per harness rules)
__device__ float g_q[QKV_ELEMS];
__device__ float g_k[QKV_ELEMS];
__device__ float g_v[QKV_ELEMS];
__device__ float g_attn[QKV_ELEMS];

// ---------------------------------------------------------------------------
// GEMM: C[M,N] = A[M,K] * B[N,K]^T   (A,B,C row-major), 128x128x8 tiles,
// 256 threads, 8x8 per thread, k-major smem tiles, register prefetch.
// ---------------------------------------------------------------------------
__global__ void __launch_bounds__(256) gemm128_nt(
    const float* __restrict__ A, const float* __restrict__ B,
    float* __restrict__ C, int M, int N, int K)
{
    __shared__ float Ats[8][128];
    __shared__ float Bts[8][128];
    const int tid = threadIdx.x;
    const int tx = tid & 15;          // 0..15  -> 8 cols each
    const int ty = tid >> 4;          // 0..15  -> 8 rows each
    const int row0 = blockIdx.y * 128;
    const int col0 = blockIdx.x * 128;
    const int lr = tid >> 1;          // 0..127
    const int lc = (tid & 1) * 4;     // 0 or 4

    const float* Ap = A + (size_t)(row0 + lr) * K + lc;
    const float* Bp = B + (size_t)(col0 + lr) * K + lc;

    float acc[8][8];
#pragma unroll
    for (int i = 0; i < 8; i++)
#pragma unroll
        for (int j = 0; j < 8; j++) acc[i][j] = 0.f;

    float4 a4 = *(const float4*)Ap;
    float4 b4 = *(const float4*)Bp;

    for (int k0 = 0;;) {
        Ats[lc + 0][lr] = a4.x; Ats[lc + 1][lr] = a4.y;
        Ats[lc + 2][lr] = a4.z; Ats[lc + 3][lr] = a4.w;
        Bts[lc + 0][lr] = b4.x; Bts[lc + 1][lr] = b4.y;
        Bts[lc + 2][lr] = b4.z; Bts[lc + 3][lr] = b4.w;
        __syncthreads();
        k0 += 8;
        if (k0 < K) {
            a4 = *(const float4*)(Ap + k0);
            b4 = *(const float4*)(Bp + k0);
        }
#pragma unroll
        for (int kk = 0; kk < 8; kk++) {
            float av[8], bv[8];
            *(float4*)&av[0] = *(const float4*)&Ats[kk][ty * 8];
            *(float4*)&av[4] = *(const float4*)&Ats[kk][ty * 8 + 4];
            *(float4*)&bv[0] = *(const float4*)&Bts[kk][tx * 8];
            *(float4*)&bv[4] = *(const float4*)&Bts[kk][tx * 8 + 4];
#pragma unroll
            for (int i = 0; i < 8; i++)
#pragma unroll
                for (int j = 0; j < 8; j++)
                    acc[i][j] += av[i] * bv[j];
        }
        if (k0 >= K) break;
        __syncthreads();
    }

#pragma unroll
    for (int i = 0; i < 8; i++) {
        float* crow = C + (size_t)(row0 + ty * 8 + i) * N + col0 + tx * 8;
        float4 c0 = make_float4(acc[i][0], acc[i][1], acc[i][2], acc[i][3]);
        float4 c1 = make_float4(acc[i][4], acc[i][5], acc[i][6], acc[i][7]);
        *(float4*)crow = c0;
        *(float4*)(crow + 4) = c1;
    }
}

// ---------------------------------------------------------------------------
// GEMM: C[M,N] = A[M,K] * B[K,N]   (all row-major), same blocking.
// ---------------------------------------------------------------------------
__global__ void __launch_bounds__(256) gemm128_nn(
    const float* __restrict__ A, const float* __restrict__ B,
    float* __restrict__ C, int M, int N, int K)
{
    __shared__ float Ats[8][128];
    __shared__ float Bts[8][128];
    const int tid = threadIdx.x;
    const int tx = tid & 15;
    const int ty = tid >> 4;
    const int row0 = blockIdx.y * 128;
    const int col0 = blockIdx.x * 128;
    const int lr = tid >> 1;            // A loader: 0..127
    const int lc = (tid & 1) * 4;
    const int bkr = tid >> 5;           // B loader: k row 0..7
    const int bnc = (tid & 31) * 4;     // n col 0..124

    const float* Ap = A + (size_t)(row0 + lr) * K + lc;
    const float* Bp = B + (size_t)bkr * N + col0 + bnc;

    float acc[8][8];
#pragma unroll
    for (int i = 0; i < 8; i++)
#pragma unroll
        for (int j = 0; j < 8; j++) acc[i][j] = 0.f;

    float4 a4 = *(const float4*)Ap;
    float4 b4 = *(const float4*)Bp;

    for (int k0 = 0;;) {
        Ats[lc + 0][lr] = a4.x; Ats[lc + 1][lr] = a4.y;
        Ats[lc + 2][lr] = a4.z; Ats[lc + 3][lr] = a4.w;
        *(float4*)&Bts[bkr][bnc] = b4;
        __syncthreads();
        k0 += 8;
        if (k0 < K) {
            a4 = *(const float4*)(Ap + k0);
            b4 = *(const float4*)(Bp + (size_t)k0 * N);
        }
#pragma unroll
        for (int kk = 0; kk < 8; kk++) {
            float av[8], bv[8];
            *(float4*)&av[0] = *(const float4*)&Ats[kk][ty * 8];
            *(float4*)&av[4] = *(const float4*)&Ats[kk][ty * 8 + 4];
            *(float4*)&bv[0] = *(const float4*)&Bts[kk][tx * 8];
            *(float4*)&bv[4] = *(const float4*)&Bts[kk][tx * 8 + 4];
#pragma unroll
            for (int i = 0; i < 8; i++)
#pragma unroll
                for (int j = 0; j < 8; j++)
                    acc[i][j] += av[i] * bv[j];
        }
        if (k0 >= K) break;
        __syncthreads();
    }

#pragma unroll
    for (int i = 0; i < 8; i++) {
        float* crow = C + (size_t)(row0 + ty * 8 + i) * N + col0 + tx * 8;
        float4 c0 = make_float4(acc[i][0], acc[i][1], acc[i][2], acc[i][3]);
        float4 c1 = make_float4(acc[i][4], acc[i][5], acc[i][6], acc[i][7]);
        *(float4*)crow = c0;
        *(float4*)(crow + 4) = c1;
    }
}

// ---------------------------------------------------------------------------
// Flash attention (causal). One block = 128 q rows of one (b,h).
// 256 threads: ty(0..15) owns 8 q-rows, tx(0..15) owns 4 cols (kv or dh).
// Online softmax fully in registers; row reductions via shfl within the
// 16-lane group that owns the row.
// smem floats: Qs 128x65, Ks 64x65, Vs 64x64, Ps 128x65  => 99584 bytes
// ---------------------------------------------------------------------------
#define ATTN_SMEM_FLOATS (128 * 65 + 64 * 65 + 64 * 64 + 128 * 65)
#define ATTN_SMEM_BYTES  (ATTN_SMEM_FLOATS * 4)

__global__ void __launch_bounds__(256) attn_kernel(
    const float* __restrict__ Q, const float* __restrict__ K,
    const float* __restrict__ V, float* __restrict__ O)
{
    extern __shared__ float sm[];
    float* Qs = sm;                    // [128][65]
    float* Ks = sm + 128 * 65;         // [64][65]
    float* Vs = Ks + 64 * 65;          // [64][64]
    float* Ps = Vs + 64 * 64;          // [128][65]

    const int tid = threadIdx.x;
    const int tx = tid & 15;
    const int ty = tid >> 4;
    const int qt = blockIdx.x;            // 0..15
    const int bh = blockIdx.y;            // 0..31
    const int b = bh >> 4, h = bh & 15;
    const int q0 = qt * 128;
    const size_t base = (size_t)b * S_ * (H_ * DH_) + (size_t)h * DH_;

    // Load Q tile [128 x 64] into padded smem
    {
        const int r = tid >> 4;            // 0..15
        const int c = (tid & 15) << 2;     // 0..60
#pragma unroll
        for (int rr = 0; rr < 128; rr += 16) {
            float4 v4 = *(const float4*)(Q + base + (size_t)(q0 + rr + r) * (H_ * DH_) + c);
            float* dst = &Qs[(rr + r) * 65 + c];
            dst[0] = v4.x; dst[1] = v4.y; dst[2] = v4.z; dst[3] = v4.w;
        }
    }

    float o[8][4];
    float m[8], l[8];
#pragma unroll
    for (int i = 0; i < 8; i++) {
        m[i] = -1e30f; l[i] = 0.f;
#pragma unroll
        for (int j = 0; j < 4; j++) o[i][j] = 0.f;
    }
    const int row_base = ty * 8;
    const int ktiles = (q0 + 128) / 64;    // 2*(qt+1)

    for (int kt = 0; kt < ktiles; kt++) {
        const int kv0 = kt * 64;
        __syncthreads();   // protect smem reuse (also orders Q load on iter 0)
        // Load K [64x64]->pad65, V [64x64]
        {
            const int r = tid >> 4;
            const int c = (tid & 15) << 2;
#pragma unroll
            for (int rr = 0; rr < 64; rr += 16) {
                float4 k4 = *(const float4*)(K + base + (size_t)(kv0 + rr + r) * (H_ * DH_) + c);
                float* kd = &Ks[(rr + r) * 65 + c];
                kd[0] = k4.x; kd[1] = k4.y; kd[2] = k4.z; kd[3] = k4.w;
                *(float4*)&Vs[(rr + r) * 64 + c] =
                    *(const float4*)(V + base + (size_t)(kv0 + rr + r) * (H_ * DH_) + c);
            }
        }
        __syncthreads();

        // S = Q K^T  (rows: row_base+i, cols: tx*4+j)
        float s[8][4];
#pragma unroll
        for (int i = 0; i < 8; i++)
#pragma unroll
            for (int j = 0; j < 4; j++) s[i][j] = 0.f;

#pragma unroll 4
        for (int d = 0; d < 64; d++) {
            float qv[8], kv[4];
#pragma unroll
            for (int i = 0; i < 8; i++) qv[i] = Qs[(row_base + i) * 65 + d];
#pragma unroll
            for (int j = 0; j < 4; j++) kv[j] = Ks[(tx * 4 + j) * 65 + d];
#pragma unroll
            for (int i = 0; i < 8; i++)
#pragma unroll
                for (int j = 0; j < 4; j++)
                    s[i][j] += qv[i] * kv[j];
        }

        const float scale = 0.125f;  // 1/sqrt(64)
        if (kv0 + 63 > q0) {
#pragma unroll
            for (int i = 0; i < 8; i++) {
                const int qg = q0 + row_base + i;
#pragma unroll
                for (int j = 0; j < 4; j++) {
                    const int kg = kv0 + tx * 4 + j;
                    s[i][j] = (kg <= qg) ? s[i][j] * scale : -1e30f;
                }
            }
        } else {
#pragma unroll
            for (int i = 0; i < 8; i++)
#pragma unroll
                for (int j = 0; j < 4; j++) s[i][j] *= scale;
        }

        // Online softmax per row (state replicated across the 16 tx lanes)
#pragma unroll
        for (int i = 0; i < 8; i++) {
            float rmax = fmaxf(fmaxf(s[i][0], s[i][1]), fmaxf(s[i][2], s[i][3]));
#pragma unroll
            for (int off = 1; off < 16; off <<= 1)
                rmax = fmaxf(rmax, __shfl_xor_sync(0xffffffffu, rmax, off));
            const float mnew = fmaxf(m[i], rmax);
            const float corr = __expf(m[i] - mnew);
            float psum = 0.f;
#pragma unroll
            for (int j = 0; j < 4; j++) {
                const float p = __expf(s[i][j] - mnew);
                s[i][j] = p;
                psum += p;
            }
#pragma unroll
            for (int off = 1; off < 16; off <<= 1)
                psum += __shfl_xor_sync(0xffffffffu, psum, off);
            l[i] = l[i] * corr + psum;
            m[i] = mnew;
#pragma unroll
            for (int j = 0; j < 4; j++) o[i][j] *= corr;
        }

        // Write P (each row written & read by the same 16-lane group)
#pragma unroll
        for (int i = 0; i < 8; i++)
#pragma unroll
            for (int j = 0; j < 4; j++)
                Ps[(row_base + i) * 65 + tx * 4 + j] = s[i][j];
        __syncwarp();

        // O += P V   (rows: row_base+i, dh cols: tx*4+j)
#pragma unroll 4
        for (int kv = 0; kv < 64; kv++) {
            float pv[8];
#pragma unroll
            for (int i = 0; i < 8; i++) pv[i] = Ps[(row_base + i) * 65 + kv];
            float vv[4];
            *(float4*)vv = *(const float4*)&Vs[kv * 64 + tx * 4];
#pragma unroll
            for (int i = 0; i < 8; i++)
#pragma unroll
                for (int j = 0; j < 4; j++)
                    o[i][j] += pv[i] * vv[j];
        }
    }

    // Normalize + store [b,s,h,e]
#pragma unroll
    for (int i = 0; i < 8; i++) {
        const float inv = 1.f / l[i];
        const int qg = q0 + row_base + i;
        float4 r = make_float4(o[i][0] * inv, o[i][1] * inv,
                               o[i][2] * inv, o[i][3] * inv);
        *(float4*)(O + base + (size_t)qg * (H_ * DH_) + tx * 4) = r;
    }
}

// ---------------------------------------------------------------------------
extern "C" void kernel_launch(void* const* d_in, const int* in_sizes, int n_in,
                              void* d_out, int out_size)
{
    const float* residual = (const float*)d_in[0];
    const float* Wq = (const float*)d_in[1];
    const float* Wk = (const float*)d_in[2];
    const float* Wv = (const float*)d_in[3];
    const float* Wo = (const float*)d_in[4];
    float* out = (float*)d_out;

    float *q, *k, *v, *attn;
    cudaGetSymbolAddress((void**)&q,    g_q);
    cudaGetSymbolAddress((void**)&k,    g_k);
    cudaGetSymbolAddress((void**)&v,    g_v);
    cudaGetSymbolAddress((void**)&attn, g_attn);

    cudaFuncSetAttribute(attn_kernel,
                         cudaFuncAttributeMaxDynamicSharedMemorySize,
                         ATTN_SMEM_BYTES);

    dim3 gproj(D_ / 128, M_ / 128);   // (8, 32)
    dim3 blk(256);

    // QKV projections: q[b,s,h,e] = residual[b,s,:] . Wq[h,e,:]
    gemm128_nt<<<gproj, blk>>>(residual, Wq, q, M_, H_ * DH_, D_);
    gemm128_nt<<<gproj, blk>>>(residual, Wk, k, M_, H_ * DH_, D_);
    gemm128_nt<<<gproj, blk>>>(residual, Wv, v, M_, H_ * DH_, D_);

    // Causal flash attention
    dim3 gattn(S_ / 128, B_ * H_);    // (16, 32)
    attn_kernel<<<gattn, blk, ATTN_SMEM_BYTES>>>(q, k, v, attn);

    // Output projection: out = attn [4096,1024] @ Wo [1024,1024]
    gemm128_nn<<<gproj, blk>>>(attn, Wo, out, M_, D_, H_ * DH_);
}

// round 4
// speedup vs baseline: 1.5906x; 1.5906x over previous
#include <cuda_runtime.h>
#include <cuda_bf16.h>
#include <cstdint>

// Problem: B=2, S=2048, D=1024, H=16, Dh=64, fp32.
// out = W_O-proj( causal-softmax( (R Wq^T)(R Wk^T)^T / 8 ) (R Wv^T) )

#define B_   2
#define S_   2048
#define D_   1024
#define H_   16
#define DH_  64
#define M_   (B_ * S_)          // 4096 rows

#define QKV_ELEMS (B_ * S_ * H_ * DH_)   // 4,194,304 floats

// Scratch (allocation-free per harness rules)
__device__ float g_q[QKV_ELEMS];
__device__ float g_k[QKV_ELEMS];
__device__ float g_v[QKV_ELEMS];
__device__ float g_attn[QKV_ELEMS];
__device__ float g_woT[D_ * D_];         // Wo^T [d][he]

__device__ __forceinline__ float to_tf32(float x) {
    uint32_t r;
    asm("cvt.rna.tf32.f32 %0, %1;" : "=r"(r) : "f"(x));
    return __uint_as_float(r);
}

// mma.sync m16n8k8 tf32: D += A*B, A row-major m16k8 frag, B k8n8 frag.
__device__ __forceinline__ void mma_tf32(float* d, const float* a, const float* b) {
    asm volatile(
        "mma.sync.aligned.m16n8k8.row.col.f32.tf32.tf32.f32 "
        "{%0,%1,%2,%3}, {%4,%5,%6,%7}, {%8,%9}, {%0,%1,%2,%3};"
        : "+f"(d[0]), "+f"(d[1]), "+f"(d[2]), "+f"(d[3])
        : "r"(__float_as_uint(a[0])), "r"(__float_as_uint(a[1])),
          "r"(__float_as_uint(a[2])), "r"(__float_as_uint(a[3])),
          "r"(__float_as_uint(b[0])), "r"(__float_as_uint(b[1])));
}

// ===========================================================================
// tf32 mma.sync GEMM: C[M,N] = A[M,K] . B[N,K]^T  (all row-major, fp32 I/O)
// 128x128 block tile, BK=32, 256 threads (8 warps @ 64x32), reg prefetch,
// cvt.rna.tf32 on smem store. Smem stride 36 -> conflict-free frag loads.
// grid = (N/128, M/128)
// ===========================================================================
#define GST 36          // smem row stride (floats)

__global__ void __launch_bounds__(256) gemm_mma_nt(
    const float* __restrict__ A, const float* __restrict__ B,
    float* __restrict__ C, int M, int N, int K)
{
    __shared__ float As[128 * GST];
    __shared__ float Bs[128 * GST];

    const int tid = threadIdx.x;
    const int lane = tid & 31;
    const int w = tid >> 5;
    const int wm = (w & 1) * 64;     // warp row offset (2 warps over M)
    const int wn = (w >> 1) * 32;    // warp col offset (4 warps over N)
    const int row0 = blockIdx.y * 128;
    const int col0 = blockIdx.x * 128;

    const int ar = tid >> 3;         // loader row 0..31
    const int ac = (tid & 7) * 4;    // loader col 0,4,...,28

    const float* Ap = A + (size_t)(row0 + ar) * K + ac;
    const float* Bp = B + (size_t)(col0 + ar) * K + ac;

    float4 pa[4], pb[4];
#pragma unroll
    for (int p = 0; p < 4; p++) {
        pa[p] = *(const float4*)(Ap + (size_t)p * 32 * K);
        pb[p] = *(const float4*)(Bp + (size_t)p * 32 * K);
    }

    float acc[4][4][4];
#pragma unroll
    for (int mi = 0; mi < 4; mi++)
#pragma unroll
        for (int ni = 0; ni < 4; ni++)
#pragma unroll
            for (int e = 0; e < 4; e++) acc[mi][ni][e] = 0.f;

    const int gr = lane >> 2;        // 0..7
    const int gc = lane & 3;         // 0..3
    const int iters = K / 32;

    for (int kt = 0;;) {
        // store prefetched regs -> smem (with tf32 RNA rounding)
#pragma unroll
        for (int p = 0; p < 4; p++) {
            const int r = ar + p * 32;
            float4 va = pa[p], vb = pb[p];
            va.x = to_tf32(va.x); va.y = to_tf32(va.y);
            va.z = to_tf32(va.z); va.w = to_tf32(va.w);
            vb.x = to_tf32(vb.x); vb.y = to_tf32(vb.y);
            vb.z = to_tf32(vb.z); vb.w = to_tf32(vb.w);
            *(float4*)&As[r * GST + ac] = va;
            *(float4*)&Bs[r * GST + ac] = vb;
        }
        __syncthreads();

        kt++;
        if (kt < iters) {
#pragma unroll
            for (int p = 0; p < 4; p++) {
                pa[p] = *(const float4*)(Ap + kt * 32 + (size_t)p * 32 * K);
                pb[p] = *(const float4*)(Bp + kt * 32 + (size_t)p * 32 * K);
            }
        }

        // compute: 4 k8-steps over the 32-wide tile
#pragma unroll
        for (int ks = 0; ks < 4; ks++) {
            const int k0 = ks * 8 + gc;
            float af[4][4];
#pragma unroll
            for (int mi = 0; mi < 4; mi++) {
                const float* ap = &As[(wm + mi * 16 + gr) * GST + k0];
                af[mi][0] = ap[0];
                af[mi][1] = ap[8 * GST];
                af[mi][2] = ap[4];
                af[mi][3] = ap[8 * GST + 4];
            }
            float bf[4][2];
#pragma unroll
            for (int ni = 0; ni < 4; ni++) {
                const float* bp = &Bs[(wn + ni * 8 + gr) * GST + k0];
                bf[ni][0] = bp[0];
                bf[ni][1] = bp[4];
            }
#pragma unroll
            for (int mi = 0; mi < 4; mi++)
#pragma unroll
                for (int ni = 0; ni < 4; ni++)
                    mma_tf32(acc[mi][ni], af[mi], bf[ni]);
        }

        if (kt >= iters) break;
        __syncthreads();
    }

    // epilogue: c0,c1 = (row, 2gc), (row, 2gc+1); c2,c3 = (row+8, ...)
#pragma unroll
    for (int mi = 0; mi < 4; mi++) {
        const int r = row0 + wm + mi * 16 + gr;
#pragma unroll
        for (int ni = 0; ni < 4; ni++) {
            const int c = col0 + wn + ni * 8 + 2 * gc;
            *(float2*)(C + (size_t)r * N + c) =
                make_float2(acc[mi][ni][0], acc[mi][ni][1]);
            *(float2*)(C + (size_t)(r + 8) * N + c) =
                make_float2(acc[mi][ni][2], acc[mi][ni][3]);
        }
    }
}

// ===========================================================================
// W_O transpose: woT[d][he] = Wo[he][d]
// ===========================================================================
__global__ void transpose_k(const float* __restrict__ in,
                            float* __restrict__ out)
{
    __shared__ float t[32][33];
    const int bx = blockIdx.x * 32, by = blockIdx.y * 32;
    const int x = threadIdx.x, y = threadIdx.y;
#pragma unroll
    for (int j = 0; j < 32; j += 8)
        t[y + j][x] = in[(size_t)(by + y + j) * D_ + bx + x];
    __syncthreads();
#pragma unroll
    for (int j = 0; j < 32; j += 8)
        out[(size_t)(bx + y + j) * D_ + by + x] = t[x][y + j];
}

// ===========================================================================
// Flash attention (causal) — unchanged from Round 2 (passing at 669us)
// ===========================================================================
#define ATTN_SMEM_FLOATS (128 * 65 + 64 * 65 + 64 * 64 + 128 * 65)
#define ATTN_SMEM_BYTES  (ATTN_SMEM_FLOATS * 4)

__global__ void __launch_bounds__(256) attn_kernel(
    const float* __restrict__ Q, const float* __restrict__ K,
    const float* __restrict__ V, float* __restrict__ O)
{
    extern __shared__ float sm[];
    float* Qs = sm;
    float* Ks = sm + 128 * 65;
    float* Vs = Ks + 64 * 65;
    float* Ps = Vs + 64 * 64;

    const int tid = threadIdx.x;
    const int tx = tid & 15;
    const int ty = tid >> 4;
    const int qt = blockIdx.x;
    const int bh = blockIdx.y;
    const int b = bh >> 4, h = bh & 15;
    const int q0 = qt * 128;
    const size_t base = (size_t)b * S_ * (H_ * DH_) + (size_t)h * DH_;

    {
        const int r = tid >> 4;
        const int c = (tid & 15) << 2;
#pragma unroll
        for (int rr = 0; rr < 128; rr += 16) {
            float4 v4 = *(const float4*)(Q + base + (size_t)(q0 + rr + r) * (H_ * DH_) + c);
            float* dst = &Qs[(rr + r) * 65 + c];
            dst[0] = v4.x; dst[1] = v4.y; dst[2] = v4.z; dst[3] = v4.w;
        }
    }

    float o[8][4];
    float m[8], l[8];
#pragma unroll
    for (int i = 0; i < 8; i++) {
        m[i] = -1e30f; l[i] = 0.f;
#pragma unroll
        for (int j = 0; j < 4; j++) o[i][j] = 0.f;
    }
    const int row_base = ty * 8;
    const int ktiles = (q0 + 128) / 64;

    for (int kt = 0; kt < ktiles; kt++) {
        const int kv0 = kt * 64;
        __syncthreads();
        {
            const int r = tid >> 4;
            const int c = (tid & 15) << 2;
#pragma unroll
            for (int rr = 0; rr < 64; rr += 16) {
                float4 k4 = *(const float4*)(K + base + (size_t)(kv0 + rr + r) * (H_ * DH_) + c);
                float* kd = &Ks[(rr + r) * 65 + c];
                kd[0] = k4.x; kd[1] = k4.y; kd[2] = k4.z; kd[3] = k4.w;
                *(float4*)&Vs[(rr + r) * 64 + c] =
                    *(const float4*)(V + base + (size_t)(kv0 + rr + r) * (H_ * DH_) + c);
            }
        }
        __syncthreads();

        float s[8][4];
#pragma unroll
        for (int i = 0; i < 8; i++)
#pragma unroll
            for (int j = 0; j < 4; j++) s[i][j] = 0.f;

#pragma unroll 4
        for (int d = 0; d < 64; d++) {
            float qv[8], kv[4];
#pragma unroll
            for (int i = 0; i < 8; i++) qv[i] = Qs[(row_base + i) * 65 + d];
#pragma unroll
            for (int j = 0; j < 4; j++) kv[j] = Ks[(tx * 4 + j) * 65 + d];
#pragma unroll
            for (int i = 0; i < 8; i++)
#pragma unroll
                for (int j = 0; j < 4; j++)
                    s[i][j] += qv[i] * kv[j];
        }

        const float scale = 0.125f;
        if (kv0 + 63 > q0) {
#pragma unroll
            for (int i = 0; i < 8; i++) {
                const int qg = q0 + row_base + i;
#pragma unroll
                for (int j = 0; j < 4; j++) {
                    const int kg = kv0 + tx * 4 + j;
                    s[i][j] = (kg <= qg) ? s[i][j] * scale : -1e30f;
                }
            }
        } else {
#pragma unroll
            for (int i = 0; i < 8; i++)
#pragma unroll
                for (int j = 0; j < 4; j++) s[i][j] *= scale;
        }

#pragma unroll
        for (int i = 0; i < 8; i++) {
            float rmax = fmaxf(fmaxf(s[i][0], s[i][1]), fmaxf(s[i][2], s[i][3]));
#pragma unroll
            for (int off = 1; off < 16; off <<= 1)
                rmax = fmaxf(rmax, __shfl_xor_sync(0xffffffffu, rmax, off));
            const float mnew = fmaxf(m[i], rmax);
            const float corr = __expf(m[i] - mnew);
            float psum = 0.f;
#pragma unroll
            for (int j = 0; j < 4; j++) {
                const float p = __expf(s[i][j] - mnew);
                s[i][j] = p;
                psum += p;
            }
#pragma unroll
            for (int off = 1; off < 16; off <<= 1)
                psum += __shfl_xor_sync(0xffffffffu, psum, off);
            l[i] = l[i] * corr + psum;
            m[i] = mnew;
#pragma unroll
            for (int j = 0; j < 4; j++) o[i][j] *= corr;
        }

#pragma unroll
        for (int i = 0; i < 8; i++)
#pragma unroll
            for (int j = 0; j < 4; j++)
                Ps[(row_base + i) * 65 + tx * 4 + j] = s[i][j];
        __syncwarp();

#pragma unroll 4
        for (int kv = 0; kv < 64; kv++) {
            float pv[8];
#pragma unroll
            for (int i = 0; i < 8; i++) pv[i] = Ps[(row_base + i) * 65 + kv];
            float vv[4];
            *(float4*)vv = *(const float4*)&Vs[kv * 64 + tx * 4];
#pragma unroll
            for (int i = 0; i < 8; i++)
#pragma unroll
                for (int j = 0; j < 4; j++)
                    o[i][j] += pv[i] * vv[j];
        }
    }

#pragma unroll
    for (int i = 0; i < 8; i++) {
        const float inv = 1.f / l[i];
        const int qg = q0 + row_base + i;
        float4 r = make_float4(o[i][0] * inv, o[i][1] * inv,
                               o[i][2] * inv, o[i][3] * inv);
        *(float4*)(O + base + (size_t)qg * (H_ * DH_) + tx * 4) = r;
    }
}

// ===========================================================================
// Host side
// ===========================================================================
extern "C" void kernel_launch(void* const* d_in, const int* in_sizes, int n_in,
                              void* d_out, int out_size)
{
    const float* residual = (const float*)d_in[0];
    const float* Wq = (const float*)d_in[1];
    const float* Wk = (const float*)d_in[2];
    const float* Wv = (const float*)d_in[3];
    const float* Wo = (const float*)d_in[4];
    float* out = (float*)d_out;

    float *q, *k, *v, *attn, *woT;
    cudaGetSymbolAddress((void**)&q,    g_q);
    cudaGetSymbolAddress((void**)&k,    g_k);
    cudaGetSymbolAddress((void**)&v,    g_v);
    cudaGetSymbolAddress((void**)&attn, g_attn);
    cudaGetSymbolAddress((void**)&woT,  g_woT);

    cudaFuncSetAttribute(attn_kernel,
                         cudaFuncAttributeMaxDynamicSharedMemorySize,
                         ATTN_SMEM_BYTES);

    dim3 blk(256);
    dim3 gg(D_ / 128, M_ / 128);      // (8, 32)
    dim3 gattn(S_ / 128, B_ * H_);    // (16, 32)

    // W_O transpose: woT[d][he] = Wo[(he)][d]
    transpose_k<<<dim3(32, 32), dim3(32, 8)>>>(Wo, woT);

    // QKV projections (tf32 mma): x[b,s,h,e] = residual[bs,:] . W[he,:]
    gemm_mma_nt<<<gg, blk>>>(residual, Wq, q, M_, D_, D_);
    gemm_mma_nt<<<gg, blk>>>(residual, Wk, k, M_, D_, D_);
    gemm_mma_nt<<<gg, blk>>>(residual, Wv, v, M_, D_, D_);

    // Causal flash attention
    attn_kernel<<<gattn, blk, ATTN_SMEM_BYTES>>>(q, k, v, attn);

    // Output projection: out[m,d] = attn[m,:] . woT[d,:]
    gemm_mma_nt<<<gg, blk>>>(attn, woT, out, M_, D_, D_);
}

// round 5
// speedup vs baseline: 2.8480x; 1.7905x over previous
#include <cuda_runtime.h>
#include <cuda_bf16.h>
#include <cstdint>

// Problem: B=2, S=2048, D=1024, H=16, Dh=64, fp32.

#define B_   2
#define S_   2048
#define D_   1024
#define H_   16
#define DH_  64
#define HD_  (H_ * DH_)          // 1024
#define M_   (B_ * S_)           // 4096

#define QKV_ELEMS (B_ * S_ * HD_)

__device__ float g_q[QKV_ELEMS];
__device__ float g_k[QKV_ELEMS];
__device__ float g_v[QKV_ELEMS];
__device__ float g_attn[QKV_ELEMS];
__device__ float g_woT[D_ * D_];

__device__ __forceinline__ float to_tf32(float x) {
    uint32_t r;
    asm("cvt.rna.tf32.f32 %0, %1;" : "=r"(r) : "f"(x));
    return __uint_as_float(r);
}

// mma.sync m16n8k8 tf32 (fragment mapping validated in R4):
// A: a0=A[gr][gc] a1=A[gr+8][gc] a2=A[gr][gc+4] a3=A[gr+8][gc+4]
// B: b0=B[n=gr][k=gc] b1=B[n=gr][k=gc+4]   (B stored row-major [N][K])
// C: c0=C[gr][2gc] c1=C[gr][2gc+1] c2=C[gr+8][2gc] c3=C[gr+8][2gc+1]
__device__ __forceinline__ void mma_tf32(float* d, const float* a, const float* b) {
    asm volatile(
        "mma.sync.aligned.m16n8k8.row.col.f32.tf32.tf32.f32 "
        "{%0,%1,%2,%3}, {%4,%5,%6,%7}, {%8,%9}, {%0,%1,%2,%3};"
        : "+f"(d[0]), "+f"(d[1]), "+f"(d[2]), "+f"(d[3])
        : "r"(__float_as_uint(a[0])), "r"(__float_as_uint(a[1])),
          "r"(__float_as_uint(a[2])), "r"(__float_as_uint(a[3])),
          "r"(__float_as_uint(b[0])), "r"(__float_as_uint(b[1])));
}

// ===========================================================================
// tf32 mma GEMM body: C[M,N] = A[M,K] . B[N,K]^T  (row-major fp32 I/O)
// 128x128 tile, BK=32, 256 threads, 8 warps @ 64x32.
// ===========================================================================
#define GST 36

__device__ __forceinline__ void gemm_body(
    const float* __restrict__ A, const float* __restrict__ B,
    float* __restrict__ C, int M, int N, int K)
{
    __shared__ float As[128 * GST];
    __shared__ float Bs[128 * GST];

    const int tid = threadIdx.x;
    const int lane = tid & 31;
    const int w = tid >> 5;
    const int wm = (w & 1) * 64;
    const int wn = (w >> 1) * 32;
    const int row0 = blockIdx.y * 128;
    const int col0 = blockIdx.x * 128;

    const int ar = tid >> 3;
    const int ac = (tid & 7) * 4;

    const float* Ap = A + (size_t)(row0 + ar) * K + ac;
    const float* Bp = B + (size_t)(col0 + ar) * K + ac;

    float4 pa[4], pb[4];
#pragma unroll
    for (int p = 0; p < 4; p++) {
        pa[p] = *(const float4*)(Ap + (size_t)p * 32 * K);
        pb[p] = *(const float4*)(Bp + (size_t)p * 32 * K);
    }

    float acc[4][4][4];
#pragma unroll
    for (int mi = 0; mi < 4; mi++)
#pragma unroll
        for (int ni = 0; ni < 4; ni++)
#pragma unroll
            for (int e = 0; e < 4; e++) acc[mi][ni][e] = 0.f;

    const int gr = lane >> 2;
    const int gc = lane & 3;
    const int iters = K / 32;

    for (int kt = 0;;) {
#pragma unroll
        for (int p = 0; p < 4; p++) {
            const int r = ar + p * 32;
            float4 va = pa[p], vb = pb[p];
            va.x = to_tf32(va.x); va.y = to_tf32(va.y);
            va.z = to_tf32(va.z); va.w = to_tf32(va.w);
            vb.x = to_tf32(vb.x); vb.y = to_tf32(vb.y);
            vb.z = to_tf32(vb.z); vb.w = to_tf32(vb.w);
            *(float4*)&As[r * GST + ac] = va;
            *(float4*)&Bs[r * GST + ac] = vb;
        }
        __syncthreads();

        kt++;
        if (kt < iters) {
#pragma unroll
            for (int p = 0; p < 4; p++) {
                pa[p] = *(const float4*)(Ap + kt * 32 + (size_t)p * 32 * K);
                pb[p] = *(const float4*)(Bp + kt * 32 + (size_t)p * 32 * K);
            }
        }

#pragma unroll
        for (int ks = 0; ks < 4; ks++) {
            const int k0 = ks * 8 + gc;
            float af[4][4];
#pragma unroll
            for (int mi = 0; mi < 4; mi++) {
                const float* ap = &As[(wm + mi * 16 + gr) * GST + k0];
                af[mi][0] = ap[0];
                af[mi][1] = ap[8 * GST];
                af[mi][2] = ap[4];
                af[mi][3] = ap[8 * GST + 4];
            }
            float bf[4][2];
#pragma unroll
            for (int ni = 0; ni < 4; ni++) {
                const float* bp = &Bs[(wn + ni * 8 + gr) * GST + k0];
                bf[ni][0] = bp[0];
                bf[ni][1] = bp[4];
            }
#pragma unroll
            for (int mi = 0; mi < 4; mi++)
#pragma unroll
                for (int ni = 0; ni < 4; ni++)
                    mma_tf32(acc[mi][ni], af[mi], bf[ni]);
        }

        if (kt >= iters) break;
        __syncthreads();
    }

#pragma unroll
    for (int mi = 0; mi < 4; mi++) {
        const int r = row0 + wm + mi * 16 + gr;
#pragma unroll
        for (int ni = 0; ni < 4; ni++) {
            const int c = col0 + wn + ni * 8 + 2 * gc;
            *(float2*)(C + (size_t)r * N + c) =
                make_float2(acc[mi][ni][0], acc[mi][ni][1]);
            *(float2*)(C + (size_t)(r + 8) * N + c) =
                make_float2(acc[mi][ni][2], acc[mi][ni][3]);
        }
    }
}

__global__ void __launch_bounds__(256) gemm_mma_nt(
    const float* __restrict__ A, const float* __restrict__ B,
    float* __restrict__ C, int M, int N, int K)
{
    gemm_body(A, B, C, M, N, K);
}

// Fused QKV: blockIdx.z selects weight/output.
__global__ void __launch_bounds__(256) gemm_mma_qkv(
    const float* __restrict__ A,
    const float* __restrict__ Wq, const float* __restrict__ Wk,
    const float* __restrict__ Wv,
    float* __restrict__ q, float* __restrict__ k, float* __restrict__ v,
    int M, int N, int K)
{
    const int z = blockIdx.z;
    const float* Bp = (z == 0) ? Wq : (z == 1) ? Wk : Wv;
    float* Cp = (z == 0) ? q : (z == 1) ? k : v;
    gemm_body(A, Bp, Cp, M, N, K);
}

// ===========================================================================
// W_O transpose
// ===========================================================================
__global__ void transpose_k(const float* __restrict__ in,
                            float* __restrict__ out)
{
    __shared__ float t[32][33];
    const int bx = blockIdx.x * 32, by = blockIdx.y * 32;
    const int x = threadIdx.x, y = threadIdx.y;
#pragma unroll
    for (int j = 0; j < 32; j += 8)
        t[y + j][x] = in[(size_t)(by + y + j) * D_ + bx + x];
    __syncthreads();
#pragma unroll
    for (int j = 0; j < 32; j += 8)
        out[(size_t)(bx + y + j) * D_ + by + x] = t[x][y + j];
}

// ===========================================================================
// Flash attention (causal) with tf32 mma.sync.
// CTA = 128 q rows of one (b,h); 8 warps x 16 q rows; KV tile = 64.
// Smem: Ks[64][68], Vs[64][68], Ps[128][68]  (Ps doubles as Q staging)
// ===========================================================================
#define AST 68
#define ATTN_SMEM_FLOATS (64 * AST + 64 * AST + 128 * AST)
#define ATTN_SMEM_BYTES  (ATTN_SMEM_FLOATS * 4)

__global__ void __launch_bounds__(256) attn_mma(
    const float* __restrict__ Q, const float* __restrict__ K,
    const float* __restrict__ V, float* __restrict__ O)
{
    extern __shared__ float sm[];
    float* Ks = sm;                  // [64][AST]
    float* Vs = sm + 64 * AST;       // [64][AST]
    float* Ps = sm + 128 * AST;      // [128][AST] (also Q staging)

    const int tid = threadIdx.x;
    const int lane = tid & 31;
    const int w = tid >> 5;          // warp: q rows w*16..w*16+15
    const int gr = lane >> 2;        // 0..7
    const int gc = lane & 3;         // 0..3

    const int qt = blockIdx.x;
    const int bh = blockIdx.y;
    const int b = bh >> 4, h = bh & 15;
    const int q0 = qt * 128;
    const size_t base = (size_t)b * S_ * HD_ + (size_t)h * DH_;

    // ---- Stage Q into Ps (tf32-rounded), pull A-fragments to registers ----
    {
        const int r = tid >> 4;            // 0..15
        const int c = (tid & 15) << 2;     // 0..60
#pragma unroll
        for (int rr = 0; rr < 128; rr += 16) {
            float4 v4 = *(const float4*)(Q + base + (size_t)(q0 + rr + r) * HD_ + c);
            v4.x = to_tf32(v4.x); v4.y = to_tf32(v4.y);
            v4.z = to_tf32(v4.z); v4.w = to_tf32(v4.w);
            *(float4*)&Ps[(rr + r) * AST + c] = v4;
        }
    }
    __syncthreads();

    float qf[8][4];
#pragma unroll
    for (int ks = 0; ks < 8; ks++) {
        const float* qp = &Ps[(w * 16 + gr) * AST + ks * 8 + gc];
        qf[ks][0] = qp[0];
        qf[ks][1] = qp[8 * AST];
        qf[ks][2] = qp[4];
        qf[ks][3] = qp[8 * AST + 4];
    }
    __syncthreads();   // all frags read before Ps is overwritten with P

    float o[8][4];
#pragma unroll
    for (int ni = 0; ni < 8; ni++)
#pragma unroll
        for (int e = 0; e < 4; e++) o[ni][e] = 0.f;
    float m0 = -1e30f, m1 = -1e30f, l0 = 0.f, l1 = 0.f;

    const int qg0 = q0 + w * 16 + gr;
    const int qg1 = qg0 + 8;
    const int ktiles = 2 * qt + 2;

    for (int kt = 0; kt < ktiles; kt++) {
        const int kv0 = kt * 64;
        __syncthreads();   // protect Ks/Vs reuse
        // ---- Load K,V tile [64x64] (tf32-rounded) ----
        {
            const int r = tid >> 4;
            const int c = (tid & 15) << 2;
#pragma unroll
            for (int rr = 0; rr < 64; rr += 16) {
                const int row = rr + r;
                float4 k4 = *(const float4*)(K + base + (size_t)(kv0 + row) * HD_ + c);
                float4 v4 = *(const float4*)(V + base + (size_t)(kv0 + row) * HD_ + c);
                k4.x = to_tf32(k4.x); k4.y = to_tf32(k4.y);
                k4.z = to_tf32(k4.z); k4.w = to_tf32(k4.w);
                v4.x = to_tf32(v4.x); v4.y = to_tf32(v4.y);
                v4.z = to_tf32(v4.z); v4.w = to_tf32(v4.w);
                *(float4*)&Ks[row * AST + c] = k4;
                *(float4*)&Vs[row * AST + c] = v4;
            }
        }
        __syncthreads();

        // Warp-tiles entirely above the diagonal produce all-masked rows: skip.
        if (kv0 > q0 + w * 16 + 15) continue;

        // ---- S = Q . K^T  [16 x 64] per warp ----
        float s[8][4];
#pragma unroll
        for (int ni = 0; ni < 8; ni++)
#pragma unroll
            for (int e = 0; e < 4; e++) s[ni][e] = 0.f;

#pragma unroll
        for (int ks = 0; ks < 8; ks++) {
            const int k0 = ks * 8 + gc;
            float bf[8][2];
#pragma unroll
            for (int ni = 0; ni < 8; ni++) {
                const float* bp = &Ks[(ni * 8 + gr) * AST + k0];
                bf[ni][0] = bp[0];
                bf[ni][1] = bp[4];
            }
#pragma unroll
            for (int ni = 0; ni < 8; ni++)
                mma_tf32(s[ni], qf[ks], bf[ni]);
        }

        // ---- scale + causal mask ----
        const float scale = 0.125f;
        if (kv0 + 63 > q0 + w * 16) {
#pragma unroll
            for (int ni = 0; ni < 8; ni++) {
                const int c0 = kv0 + ni * 8 + 2 * gc;
                s[ni][0] = (c0     <= qg0) ? s[ni][0] * scale : -1e30f;
                s[ni][1] = (c0 + 1 <= qg0) ? s[ni][1] * scale : -1e30f;
                s[ni][2] = (c0     <= qg1) ? s[ni][2] * scale : -1e30f;
                s[ni][3] = (c0 + 1 <= qg1) ? s[ni][3] * scale : -1e30f;
            }
        } else {
#pragma unroll
            for (int ni = 0; ni < 8; ni++)
#pragma unroll
                for (int e = 0; e < 4; e++) s[ni][e] *= scale;
        }

        // ---- online softmax (rows qg0: e=0,1 and qg1: e=2,3) ----
        float rmax0 = -1e30f, rmax1 = -1e30f;
#pragma unroll
        for (int ni = 0; ni < 8; ni++) {
            rmax0 = fmaxf(rmax0, fmaxf(s[ni][0], s[ni][1]));
            rmax1 = fmaxf(rmax1, fmaxf(s[ni][2], s[ni][3]));
        }
        rmax0 = fmaxf(rmax0, __shfl_xor_sync(0xffffffffu, rmax0, 1));
        rmax0 = fmaxf(rmax0, __shfl_xor_sync(0xffffffffu, rmax0, 2));
        rmax1 = fmaxf(rmax1, __shfl_xor_sync(0xffffffffu, rmax1, 1));
        rmax1 = fmaxf(rmax1, __shfl_xor_sync(0xffffffffu, rmax1, 2));

        const float mn0 = fmaxf(m0, rmax0);
        const float mn1 = fmaxf(m1, rmax1);
        const float corr0 = __expf(m0 - mn0);
        const float corr1 = __expf(m1 - mn1);

        float ps0 = 0.f, ps1 = 0.f;
#pragma unroll
        for (int ni = 0; ni < 8; ni++) {
            s[ni][0] = __expf(s[ni][0] - mn0);
            s[ni][1] = __expf(s[ni][1] - mn0);
            s[ni][2] = __expf(s[ni][2] - mn1);
            s[ni][3] = __expf(s[ni][3] - mn1);
            ps0 += s[ni][0] + s[ni][1];
            ps1 += s[ni][2] + s[ni][3];
        }
        ps0 += __shfl_xor_sync(0xffffffffu, ps0, 1);
        ps0 += __shfl_xor_sync(0xffffffffu, ps0, 2);
        ps1 += __shfl_xor_sync(0xffffffffu, ps1, 1);
        ps1 += __shfl_xor_sync(0xffffffffu, ps1, 2);

        l0 = l0 * corr0 + ps0;  m0 = mn0;
        l1 = l1 * corr1 + ps1;  m1 = mn1;

#pragma unroll
        for (int ni = 0; ni < 8; ni++) {
            o[ni][0] *= corr0; o[ni][1] *= corr0;
            o[ni][2] *= corr1; o[ni][3] *= corr1;
        }

        // ---- P -> Ps (tf32-rounded); each warp owns its 16 rows ----
        {
            float* p0 = &Ps[(w * 16 + gr) * AST + 2 * gc];
            float* p1 = p0 + 8 * AST;
#pragma unroll
            for (int ni = 0; ni < 8; ni++) {
                *(float2*)(p0 + ni * 8) =
                    make_float2(to_tf32(s[ni][0]), to_tf32(s[ni][1]));
                *(float2*)(p1 + ni * 8) =
                    make_float2(to_tf32(s[ni][2]), to_tf32(s[ni][3]));
            }
        }
        __syncwarp();

        // ---- O += P . V  (contraction over kv, N = dh) ----
#pragma unroll
        for (int ks = 0; ks < 8; ks++) {
            const float* ap = &Ps[(w * 16 + gr) * AST + ks * 8 + gc];
            float af[4];
            af[0] = ap[0];
            af[1] = ap[8 * AST];
            af[2] = ap[4];
            af[3] = ap[8 * AST + 4];
            const float* v0 = &Vs[(ks * 8 + gc) * AST + gr];
            const float* v1 = &Vs[(ks * 8 + gc + 4) * AST + gr];
            float bf[8][2];
#pragma unroll
            for (int ni = 0; ni < 8; ni++) {
                bf[ni][0] = v0[ni * 8];
                bf[ni][1] = v1[ni * 8];
            }
#pragma unroll
            for (int ni = 0; ni < 8; ni++)
                mma_tf32(o[ni], af, bf[ni]);
        }
    }

    // ---- epilogue ----
    const float inv0 = 1.f / l0;
    const float inv1 = 1.f / l1;
#pragma unroll
    for (int ni = 0; ni < 8; ni++) {
        const int c = ni * 8 + 2 * gc;
        *(float2*)(O + base + (size_t)qg0 * HD_ + c) =
            make_float2(o[ni][0] * inv0, o[ni][1] * inv0);
        *(float2*)(O + base + (size_t)qg1 * HD_ + c) =
            make_float2(o[ni][2] * inv1, o[ni][3] * inv1);
    }
}

// ===========================================================================
// Host side
// ===========================================================================
extern "C" void kernel_launch(void* const* d_in, const int* in_sizes, int n_in,
                              void* d_out, int out_size)
{
    const float* residual = (const float*)d_in[0];
    const float* Wq = (const float*)d_in[1];
    const float* Wk = (const float*)d_in[2];
    const float* Wv = (const float*)d_in[3];
    const float* Wo = (const float*)d_in[4];
    float* out = (float*)d_out;

    float *q, *k, *v, *attn, *woT;
    cudaGetSymbolAddress((void**)&q,    g_q);
    cudaGetSymbolAddress((void**)&k,    g_k);
    cudaGetSymbolAddress((void**)&v,    g_v);
    cudaGetSymbolAddress((void**)&attn, g_attn);
    cudaGetSymbolAddress((void**)&woT,  g_woT);

    cudaFuncSetAttribute(attn_mma,
                         cudaFuncAttributeMaxDynamicSharedMemorySize,
                         ATTN_SMEM_BYTES);

    dim3 blk(256);

    // W_O transpose
    transpose_k<<<dim3(32, 32), dim3(32, 8)>>>(Wo, woT);

    // Fused QKV projections
    dim3 gqkv(D_ / 128, M_ / 128, 3);
    gemm_mma_qkv<<<gqkv, blk>>>(residual, Wq, Wk, Wv, q, k, v, M_, D_, D_);

    // Causal flash attention (tf32 mma)
    dim3 gattn(S_ / 128, B_ * H_);
    attn_mma<<<gattn, blk, ATTN_SMEM_BYTES>>>(q, k, v, attn);

    // Output projection
    dim3 gg(D_ / 128, M_ / 128);
    gemm_mma_nt<<<gg, blk>>>(attn, woT, out, M_, D_, D_);
}